// round 9
// baseline (speedup 1.0000x reference)
#include <cuda_runtime.h>

#define IN_DIM   2048
#define OUT_DIM  14951
#define THREADS  256
#define EPS      1e-12f

__global__ __launch_bounds__(THREADS)
void hc_kernel(const float* __restrict__ x,
               const float* __restrict__ scale,
               const float* __restrict__ bias,
               float* __restrict__ out)
{
    __shared__ alignas(16) float xch[IN_DIM];   // 8 KB: exchange, then shifted-y
    __shared__ float sred[THREADS / 32];
    __shared__ float sc;

    const int t    = threadIdx.x;
    const int row  = blockIdx.x;
    const int lane = t & 31;
    const int Q    = t >> 5;
    const int s    = row & 3;        // out+row*14951+j is 16B-aligned iff j ≡ s (mod 4)

    float res[8];                    // res[q] = element n = q*256 + t

    const float* __restrict__ xr = x + (size_t)row * IN_DIM;

    // ---- load (coalesced, evict-first) + sum of squares ----
    float ss = 0.f;
#pragma unroll
    for (int q = 0; q < 8; ++q) {
        float v = __ldcs(xr + q * THREADS + t);
        res[q] = v;
        ss += v * v;
    }
#pragma unroll
    for (int o = 16; o; o >>= 1) ss += __shfl_xor_sync(0xFFFFFFFFu, ss, o);
    if (lane == 0) sred[Q] = ss;
    __syncthreads();
    if (t == 0) {
        float tot = 0.f;
#pragma unroll
        for (int w = 0; w < THREADS / 32; ++w) tot += sred[w];
        sc = -scale[0] * rsqrtf(fmaxf(tot, EPS));
    }

    // ---- 3 register stages (bits 8..10 of n == bits of q) ----
#pragma unroll
    for (int B = 1; B < 8; B <<= 1) {
#pragma unroll
        for (int q = 0; q < 8; ++q) {
            if (!(q & B)) {
                float a0 = res[q], a1 = res[q | B];
                res[q]     = a0 + a1;
                res[q | B] = a0 - a1;
            }
        }
    }

    // ---- 5 shuffle stages (bits 0..4 of n == lane bits of t) ----
#pragma unroll
    for (int h = 1; h <= 16; h <<= 1) {
#pragma unroll
        for (int q = 0; q < 8; ++q) {
            float o = __shfl_xor_sync(0xFFFFFFFFu, res[q], h);
            res[q] = (t & h) ? (o - res[q]) : (res[q] + o);
        }
    }

    // ---- transpose A: bring warp-bits (5..7 of n) into register index u ----
#pragma unroll
    for (int q = 0; q < 8; ++q) xch[q * THREADS + t] = res[q];
    __syncthreads();
#pragma unroll
    for (int u = 0; u < 8; ++u) res[u] = xch[Q * THREADS + u * 32 + lane];

    // ---- 3 register stages over u (bits 5..7 of n) ----
#pragma unroll
    for (int B = 1; B < 8; B <<= 1) {
#pragma unroll
        for (int u = 0; u < 8; ++u) {
            if (!(u & B)) {
                float a0 = res[u], a1 = res[u | B];
                res[u]     = a0 + a1;
                res[u | B] = a0 - a1;
            }
        }
    }
    // now res[u] = y[Q*256 + u*32 + lane]

    // ---- transpose B (shift folded in): xch[k] = y[(k+s) & 2047] ----
    __syncthreads();                 // xch free (all reads of transpose A done)
#pragma unroll
    for (int u = 0; u < 8; ++u) {
        int k = (Q * THREADS + u * 32 + lane - s) & (IN_DIM - 1);
        xch[k] = res[u];
    }
    __syncthreads();

    // thread t owns y'[8t .. 8t+7] in registers (2 aligned LDS.128)
    float4 v0 = *reinterpret_cast<const float4*>(xch + 8 * t);
    float4 v1 = *reinterpret_cast<const float4*>(xch + 8 * t + 4);

    const float c = sc;
    float* __restrict__ orow = out + (size_t)row * OUT_DIM;

    // ---- head (j < s) and tail (j >= s+14948): scalar, read y' straight from smem ----
    if (t < s) {
        int j = t;                                   // y[j] = y'[(j - s) & 2047]
        __stcs(orow + j, fmaf(c, xch[(j - s) & (IN_DIM - 1)], __ldg(bias + j)));
    }
    if (t < 3 - s) {
        int j = s + 14948 + t;                       // y[j&2047] = y'[(j-s) & 2047]
        __stcs(orow + j, fmaf(c, xch[(14948 + t) & (IN_DIM - 1)], __ldg(bias + j)));
    }

    // ---- body: j = s + 8t + 2048*kc + {0..7}; all 16B-aligned stores ----
    // 7 full chunks, order rotated by row (decorrelates bias-line contention)
    const int cbase = row % 7;
#pragma unroll
    for (int cc = 0; cc < 7; ++cc) {
        int kc = cbase + cc;
        if (kc >= 7) kc -= 7;
        const int j0 = s + 8 * t + (kc << 11);
        float b0 = __ldg(bias + j0);
        float b1 = __ldg(bias + j0 + 1);
        float b2 = __ldg(bias + j0 + 2);
        float b3 = __ldg(bias + j0 + 3);
        float b4 = __ldg(bias + j0 + 4);
        float b5 = __ldg(bias + j0 + 5);
        float b6 = __ldg(bias + j0 + 6);
        float b7 = __ldg(bias + j0 + 7);
        __stcs(reinterpret_cast<float4*>(orow + j0),
               make_float4(fmaf(c, v0.x, b0), fmaf(c, v0.y, b1),
                           fmaf(c, v0.z, b2), fmaf(c, v0.w, b3)));
        __stcs(reinterpret_cast<float4*>(orow + j0 + 4),
               make_float4(fmaf(c, v1.x, b4), fmaf(c, v1.y, b5),
                           fmaf(c, v1.z, b6), fmaf(c, v1.w, b7)));
    }

    // ---- partial chunk kc = 7 ----
    {
        const int j0 = s + 8 * t + (7 << 11);
        if (j0 + 3 < OUT_DIM) {
            float b0 = __ldg(bias + j0);
            float b1 = __ldg(bias + j0 + 1);
            float b2 = __ldg(bias + j0 + 2);
            float b3 = __ldg(bias + j0 + 3);
            __stcs(reinterpret_cast<float4*>(orow + j0),
                   make_float4(fmaf(c, v0.x, b0), fmaf(c, v0.y, b1),
                               fmaf(c, v0.z, b2), fmaf(c, v0.w, b3)));
        }
        if (j0 + 7 < OUT_DIM) {
            float b4 = __ldg(bias + j0 + 4);
            float b5 = __ldg(bias + j0 + 5);
            float b6 = __ldg(bias + j0 + 6);
            float b7 = __ldg(bias + j0 + 7);
            __stcs(reinterpret_cast<float4*>(orow + j0 + 4),
                   make_float4(fmaf(c, v1.x, b4), fmaf(c, v1.y, b5),
                               fmaf(c, v1.z, b6), fmaf(c, v1.w, b7)));
        }
    }
}

extern "C" void kernel_launch(void* const* d_in, const int* in_sizes, int n_in,
                              void* d_out, int out_size)
{
    const float* x     = (const float*)d_in[0];
    const float* scale = (const float*)d_in[1];
    const float* bias  = (const float*)d_in[2];
    float* out = (float*)d_out;

    const int batch = in_sizes[0] / IN_DIM;     // 4096
    hc_kernel<<<batch, THREADS>>>(x, scale, bias, out);
}

// round 10
// speedup vs baseline: 1.8211x; 1.8211x over previous
#include <cuda_runtime.h>

#define IN_DIM   2048
#define OUT_DIM  14951
#define THREADS  256
#define NB4      3737            // aligned float4 body chunks per row: (14951 - s) >> 2
#define BS_PAD   3744            // padded float4s per shifted-bias copy
#define EPS      1e-12f

// 4 shifted copies of bias so every epilogue bias load is an aligned LDG.128:
// g_biasS[s][i] = bias[4i+s .. 4i+s+3]
__device__ float4 g_biasS[4][BS_PAD];

__global__ void bias_shift_kernel(const float* __restrict__ bias)
{
    int idx = blockIdx.x * blockDim.x + threadIdx.x;
    if (idx >= 4 * BS_PAD) return;
    int s = idx / BS_PAD;
    int i = idx - s * BS_PAD;
    int j = 4 * i + s;
    float4 v;
    v.x = (j     < OUT_DIM) ? bias[j]     : 0.f;
    v.y = (j + 1 < OUT_DIM) ? bias[j + 1] : 0.f;
    v.z = (j + 2 < OUT_DIM) ? bias[j + 2] : 0.f;
    v.w = (j + 3 < OUT_DIM) ? bias[j + 3] : 0.f;
    g_biasS[s][i] = v;
}

__global__ __launch_bounds__(THREADS)
void hc_kernel(const float* __restrict__ x,
               const float* __restrict__ scale,
               const float* __restrict__ bias,
               float* __restrict__ out)
{
    __shared__ alignas(16) float xch[IN_DIM];   // 8 KB: exchange, then shifted-y
    __shared__ float sred[THREADS / 32];
    __shared__ float sc;

    const int t    = threadIdx.x;
    const int row  = blockIdx.x;
    const int lane = t & 31;
    const int Q    = t >> 5;
    const int s    = row & 3;    // out + row*14951 + j is 16B-aligned iff j ≡ s (mod 4)

    float res[8];                // res[q] = element n = q*256 + t

    const float* __restrict__ xr = x + (size_t)row * IN_DIM;

    // ---- load (coalesced, evict-first) + sum of squares ----
    float ss = 0.f;
#pragma unroll
    for (int q = 0; q < 8; ++q) {
        float v = __ldcs(xr + q * THREADS + t);
        res[q] = v;
        ss += v * v;
    }
#pragma unroll
    for (int o = 16; o; o >>= 1) ss += __shfl_xor_sync(0xFFFFFFFFu, ss, o);
    if (lane == 0) sred[Q] = ss;
    __syncthreads();
    if (t == 0) {
        float tot = 0.f;
#pragma unroll
        for (int w = 0; w < THREADS / 32; ++w) tot += sred[w];
        sc = -scale[0] * rsqrtf(fmaxf(tot, EPS));
    }

    // ---- 3 register stages (bits 8..10 of n == bits of q) ----
#pragma unroll
    for (int B = 1; B < 8; B <<= 1) {
#pragma unroll
        for (int q = 0; q < 8; ++q) {
            if (!(q & B)) {
                float a0 = res[q], a1 = res[q | B];
                res[q]     = a0 + a1;
                res[q | B] = a0 - a1;
            }
        }
    }

    // ---- 5 shuffle stages (bits 0..4 of n == lane bits of t) ----
#pragma unroll
    for (int h = 1; h <= 16; h <<= 1) {
#pragma unroll
        for (int q = 0; q < 8; ++q) {
            float o = __shfl_xor_sync(0xFFFFFFFFu, res[q], h);
            res[q] = (t & h) ? (o - res[q]) : (res[q] + o);
        }
    }

    // ---- transpose A: bring warp-bits (5..7 of n) into register index u ----
#pragma unroll
    for (int q = 0; q < 8; ++q) xch[q * THREADS + t] = res[q];
    __syncthreads();
#pragma unroll
    for (int u = 0; u < 8; ++u) res[u] = xch[Q * THREADS + u * 32 + lane];

    // ---- 3 register stages over u (bits 5..7 of n) ----
#pragma unroll
    for (int B = 1; B < 8; B <<= 1) {
#pragma unroll
        for (int u = 0; u < 8; ++u) {
            if (!(u & B)) {
                float a0 = res[u], a1 = res[u | B];
                res[u]     = a0 + a1;
                res[u | B] = a0 - a1;
            }
        }
    }
    // now res[u] = y[Q*256 + u*32 + lane]

    // ---- transpose B (shift folded in): xch[k] = y[(k+s) & 2047] ----
    __syncthreads();
#pragma unroll
    for (int u = 0; u < 8; ++u) {
        int k = (Q * THREADS + u * 32 + lane - s) & (IN_DIM - 1);
        xch[k] = res[u];
    }
    __syncthreads();

    // thread t's two register-resident y float4s (j0 mod 2048 alternates 4t / 4t+1024)
    const float4 ylo = *reinterpret_cast<const float4*>(xch + 4 * t);
    const float4 yhi = *reinterpret_cast<const float4*>(xch + 4 * t + 1024);

    const float c = sc;
    float* __restrict__ orow = out + (size_t)row * OUT_DIM;

    // ---- head (j < s) and tail (j >= s+14948): scalar ----
    if (t < s) {
        int j = t;
        __stcs(orow + j, fmaf(c, xch[(j - s) & (IN_DIM - 1)], __ldg(bias + j)));
    }
    if (t < 3 - s) {
        int j = s + 4 * NB4 + t;                       // s + 14948 + t
        __stcs(orow + j, fmaf(c, xch[(4 * NB4 + t) & (IN_DIM - 1)], __ldg(bias + j)));
    }

    // ---- body: j0 = s + 4*(t + 256*mi); aligned LDG.128 bias + STG.128 out ----
    // rolled loop, iteration order rotated by row (decorrelates L2-line contention)
    const float4* __restrict__ bs = g_biasS[s];
    const int it0 = row % 15;
#pragma unroll 1
    for (int cc = 0; cc < 15; ++cc) {
        int mi = it0 + cc;
        if (mi >= 15) mi -= 15;
        int i = t + (mi << 8);
        if (i < NB4) {
            float4 bv = __ldg(bs + i);
            float4 yv = (mi & 1) ? yhi : ylo;
            float4 o4 = make_float4(fmaf(c, yv.x, bv.x), fmaf(c, yv.y, bv.y),
                                    fmaf(c, yv.z, bv.z), fmaf(c, yv.w, bv.w));
            __stcs(reinterpret_cast<float4*>(orow + s + 4 * i), o4);
        }
    }
}

extern "C" void kernel_launch(void* const* d_in, const int* in_sizes, int n_in,
                              void* d_out, int out_size)
{
    const float* x     = (const float*)d_in[0];
    const float* scale = (const float*)d_in[1];
    const float* bias  = (const float*)d_in[2];
    float* out = (float*)d_out;

    const int batch = in_sizes[0] / IN_DIM;     // 4096

    bias_shift_kernel<<<(4 * BS_PAD + THREADS - 1) / THREADS, THREADS>>>(bias);
    hc_kernel<<<batch, THREADS>>>(x, scale, bias, out);
}

// round 12
// speedup vs baseline: 1.8962x; 1.0413x over previous
#include <cuda_runtime.h>

#define IN_DIM   2048
#define OUT_DIM  14951
#define THREADS  256
#define NB4      3737            // aligned float4 body chunks per row: (14951 - s) >> 2
#define EPS      1e-12f

// Epilogue body, specialized on the per-row alignment shift S (uniform per CTA).
// Stores out[row, s+4i .. s+4i+3] = c * y' + bias[s+4i .. s+4i+3] with:
//   - aligned LDG.128 of bias4[i] (lane-contiguous)
//   - shifted window built from (bv, next lane's bv) via shfl_down
//   - aligned STG.128 (streaming)
template<int S>
__device__ __forceinline__ void epilogue_body(
    const float4* __restrict__ bias4, const float* __restrict__ bias,
    float* __restrict__ orow, float c, float4 ylo, float4 yhi,
    int t, int lane, int it0)
{
#pragma unroll 1
    for (int cc = 0; cc < 15; ++cc) {
        int mi = it0 + cc;
        if (mi >= 15) mi -= 15;
        const int i  = t + (mi << 8);
        const int ii = (i < NB4) ? i : (NB4 - 1);     // clamp: whole warp loads/shuffles
        float4 bv = __ldg(bias4 + ii);

        float w0, w1, w2, w3;
        if (S == 0) {
            w0 = bv.x; w1 = bv.y; w2 = bv.z; w3 = bv.w;
        } else {
            float n0 = 0.f, n1 = 0.f, n2 = 0.f;
            if (S >= 1) n0 = __shfl_down_sync(0xFFFFFFFFu, bv.x, 1);
            if (S >= 2) n1 = __shfl_down_sync(0xFFFFFFFFu, bv.y, 1);
            if (S >= 3) n2 = __shfl_down_sync(0xFFFFFFFFu, bv.z, 1);
            // Patch when the shuffle source is unreliable: lane 31 has no source,
            // and near the boundary (i >= NB4-1) the neighbor lane was clamped.
            // Scalar loads read bias[4*(ii+1) .. 4*(ii+1)+S-1] <= bias[14950]: in bounds.
            if (lane == 31 || i >= NB4 - 1) {
                const float* nb = bias + 4 * (ii + 1);
                if (S >= 1) n0 = __ldg(nb);
                if (S >= 2) n1 = __ldg(nb + 1);
                if (S >= 3) n2 = __ldg(nb + 2);
            }
            if (S == 1)      { w0 = bv.y; w1 = bv.z; w2 = bv.w; w3 = n0; }
            else if (S == 2) { w0 = bv.z; w1 = bv.w; w2 = n0;  w3 = n1; }
            else             { w0 = bv.w; w1 = n0;  w2 = n1;  w3 = n2; }
        }

        if (i < NB4) {
            float4 yv = (mi & 1) ? yhi : ylo;
            float4 o4 = make_float4(fmaf(c, yv.x, w0), fmaf(c, yv.y, w1),
                                    fmaf(c, yv.z, w2), fmaf(c, yv.w, w3));
            __stcs(reinterpret_cast<float4*>(orow + S + 4 * i), o4);
        }
    }
}

__global__ __launch_bounds__(THREADS)
void hc_kernel(const float* __restrict__ x,
               const float* __restrict__ scale,
               const float* __restrict__ bias,
               float* __restrict__ out)
{
    __shared__ alignas(16) float xch[IN_DIM];   // 8 KB: exchange, then shifted-y
    __shared__ float sred[THREADS / 32];
    __shared__ float sc;

    const int t    = threadIdx.x;
    const int row  = blockIdx.x;
    const int lane = t & 31;
    const int Q    = t >> 5;
    const int s    = row & 3;    // out + row*14951 + j is 16B-aligned iff j ≡ s (mod 4)

    float res[8];                // res[q] = element n = q*256 + t

    const float* __restrict__ xr = x + (size_t)row * IN_DIM;

    // ---- load (coalesced, evict-first) + sum of squares ----
    float ss = 0.f;
#pragma unroll
    for (int q = 0; q < 8; ++q) {
        float v = __ldcs(xr + q * THREADS + t);
        res[q] = v;
        ss += v * v;
    }
#pragma unroll
    for (int o = 16; o; o >>= 1) ss += __shfl_xor_sync(0xFFFFFFFFu, ss, o);
    if (lane == 0) sred[Q] = ss;
    __syncthreads();
    if (t == 0) {
        float tot = 0.f;
#pragma unroll
        for (int w = 0; w < THREADS / 32; ++w) tot += sred[w];
        sc = -scale[0] * rsqrtf(fmaxf(tot, EPS));
    }

    // ---- 3 register stages (bits 8..10 of n == bits of q) ----
#pragma unroll
    for (int B = 1; B < 8; B <<= 1) {
#pragma unroll
        for (int q = 0; q < 8; ++q) {
            if (!(q & B)) {
                float a0 = res[q], a1 = res[q | B];
                res[q]     = a0 + a1;
                res[q | B] = a0 - a1;
            }
        }
    }

    // ---- 5 shuffle stages (bits 0..4 of n == lane bits of t) ----
#pragma unroll
    for (int h = 1; h <= 16; h <<= 1) {
#pragma unroll
        for (int q = 0; q < 8; ++q) {
            float o = __shfl_xor_sync(0xFFFFFFFFu, res[q], h);
            res[q] = (t & h) ? (o - res[q]) : (res[q] + o);
        }
    }

    // ---- transpose A: bring warp-bits (5..7 of n) into register index u ----
#pragma unroll
    for (int q = 0; q < 8; ++q) xch[q * THREADS + t] = res[q];
    __syncthreads();
#pragma unroll
    for (int u = 0; u < 8; ++u) res[u] = xch[Q * THREADS + u * 32 + lane];

    // ---- 3 register stages over u (bits 5..7 of n) ----
#pragma unroll
    for (int B = 1; B < 8; B <<= 1) {
#pragma unroll
        for (int u = 0; u < 8; ++u) {
            if (!(u & B)) {
                float a0 = res[u], a1 = res[u | B];
                res[u]     = a0 + a1;
                res[u | B] = a0 - a1;
            }
        }
    }
    // now res[u] = y[Q*256 + u*32 + lane]

    // ---- transpose B (shift folded in): xch[k] = y[(k+s) & 2047] ----
    __syncthreads();
#pragma unroll
    for (int u = 0; u < 8; ++u) {
        int k = (Q * THREADS + u * 32 + lane - s) & (IN_DIM - 1);
        xch[k] = res[u];
    }
    __syncthreads();

    // thread t's two register-resident y float4s (j0 mod 2048 alternates 4t / 4t+1024)
    const float4 ylo = *reinterpret_cast<const float4*>(xch + 4 * t);
    const float4 yhi = *reinterpret_cast<const float4*>(xch + 4 * t + 1024);

    const float c = sc;
    float* __restrict__ orow = out + (size_t)row * OUT_DIM;

    // ---- head (j < s) and tail (j >= s+14948): scalar ----
    if (t < s) {
        int j = t;
        __stcs(orow + j, fmaf(c, xch[(j - s) & (IN_DIM - 1)], __ldg(bias + j)));
    }
    if (t < 3 - s) {
        int j = s + 4 * NB4 + t;                       // s + 14948 + t
        __stcs(orow + j, fmaf(c, xch[(4 * NB4 + t) & (IN_DIM - 1)], __ldg(bias + j)));
    }

    // ---- body: aligned LDG.128 bias + shuffle-shift + aligned STG.128 out ----
    const float4* __restrict__ bias4 = reinterpret_cast<const float4*>(bias);
    const int it0 = row % 15;      // rotation: decorrelates L2-line contention
    switch (s) {
        case 0: epilogue_body<0>(bias4, bias, orow, c, ylo, yhi, t, lane, it0); break;
        case 1: epilogue_body<1>(bias4, bias, orow, c, ylo, yhi, t, lane, it0); break;
        case 2: epilogue_body<2>(bias4, bias, orow, c, ylo, yhi, t, lane, it0); break;
        default: epilogue_body<3>(bias4, bias, orow, c, ylo, yhi, t, lane, it0); break;
    }
}

extern "C" void kernel_launch(void* const* d_in, const int* in_sizes, int n_in,
                              void* d_out, int out_size)
{
    const float* x     = (const float*)d_in[0];
    const float* scale = (const float*)d_in[1];
    const float* bias  = (const float*)d_in[2];
    float* out = (float*)d_out;

    const int batch = in_sizes[0] / IN_DIM;     // 4096
    hc_kernel<<<batch, THREADS>>>(x, scale, bias, out);
}